// round 2
// baseline (speedup 1.0000x reference)
#include <cuda_runtime.h>
#include <math.h>

#define NN 100000
#define EE 3200000
#define NF 256
#define NH 128
#define NC 16

// ---- static device scratch (no allocations allowed) ----
__device__ float g_deg[NN];
__device__ float g_dinv[NN];
__device__ int   g_cnt[NN];
__device__ int   g_start[NN + 1];
__device__ int   g_cursor[NN];
__device__ int   g_src[EE];
__device__ float g_w[EE];
__device__ float g_xw1[(size_t)NN * NH];   // features @ W1
__device__ float g_h[(size_t)NN * NH];     // relu(prop(xw1)+b1)
__device__ float g_hw2[(size_t)NN * NC];   // h @ W2

// ---------------------------------------------------------------- init
__global__ void k_init() {
    int i = blockIdx.x * blockDim.x + threadIdx.x;
    if (i < NN) { g_deg[i] = 1.0f; g_cnt[i] = 0; }  // deg starts at 1 (self-loop weight)
}

// ------------------------------------------------------- degree + counts
__global__ void k_deg(const int* __restrict__ ei, const float* __restrict__ ew) {
    int e = blockIdx.x * blockDim.x + threadIdx.x;
    if (e < EE) {
        int c = ei[EE + e];
        atomicAdd(&g_deg[c], ew[e]);
        atomicAdd(&g_cnt[c], 1);
    }
}

__global__ void k_dinv() {
    int i = blockIdx.x * blockDim.x + threadIdx.x;
    if (i < NN) {
        float d = g_deg[i];
        g_dinv[i] = d > 0.0f ? rsqrtf(d) : 0.0f;
    }
}

// ----------------------------------------------------- one-block exclusive scan
__global__ void k_scan() {
    __shared__ int sh[1024];
    int t = threadIdx.x;
    int running = 0;
    for (int base = 0; base < NN; base += 1024) {
        int i = base + t;
        int v = (i < NN) ? g_cnt[i] : 0;
        sh[t] = v;
        __syncthreads();
        #pragma unroll
        for (int off = 1; off < 1024; off <<= 1) {
            int x = (t >= off) ? sh[t - off] : 0;
            __syncthreads();
            sh[t] += x;
            __syncthreads();
        }
        int incl = sh[t];
        if (i < NN) {
            int ex = running + incl - v;
            g_start[i]  = ex;
            g_cursor[i] = ex;
        }
        running += sh[1023];
        __syncthreads();
    }
    if (t == 0) g_start[NN] = running;
}

// ------------------------------------------------- scatter edges into CSC + norm
__global__ void k_scatter(const int* __restrict__ ei, const float* __restrict__ ew) {
    int e = blockIdx.x * blockDim.x + threadIdx.x;
    if (e < EE) {
        int r = ei[e];
        int c = ei[EE + e];
        float nrm = g_dinv[r] * ew[e] * g_dinv[c];
        int pos = atomicAdd(&g_cursor[c], 1);
        g_src[pos] = r;
        g_w[pos]   = nrm;
    }
}

// ------------------------------------------------------------- GEMM1: X@W1
// M=100000, K=256, N=128.  BM=128, BN=128, BK=16, 8x8 per thread, 256 threads.
__global__ void __launch_bounds__(256) k_gemm1(const float* __restrict__ A,
                                               const float* __restrict__ B) {
    __shared__ float As[16][128];
    __shared__ float Bs[16][128];
    const int tid  = threadIdx.x;
    const int trow = tid >> 4;   // 0..15
    const int tcol = tid & 15;   // 0..15
    const int row0 = blockIdx.x * 128;

    float acc[8][8];
    #pragma unroll
    for (int i = 0; i < 8; i++)
        #pragma unroll
        for (int j = 0; j < 8; j++) acc[i][j] = 0.0f;

    for (int k0 = 0; k0 < NF; k0 += 16) {
        #pragma unroll
        for (int l = 0; l < 2; l++) {            // A tile: 512 float4
            int f4 = tid + l * 256;
            int r  = f4 >> 2;
            int kc = (f4 & 3) << 2;
            int gr = row0 + r;
            float4 v = make_float4(0.f, 0.f, 0.f, 0.f);
            if (gr < NN) v = *(const float4*)(A + (size_t)gr * NF + k0 + kc);
            As[kc + 0][r] = v.x; As[kc + 1][r] = v.y;
            As[kc + 2][r] = v.z; As[kc + 3][r] = v.w;
        }
        #pragma unroll
        for (int l = 0; l < 2; l++) {            // B tile: 512 float4
            int f4 = tid + l * 256;
            int r  = f4 >> 5;
            int c4 = f4 & 31;
            float4 v = *(const float4*)(B + (size_t)(k0 + r) * NH + c4 * 4);
            *(((float4*)&Bs[r][0]) + c4) = v;
        }
        __syncthreads();
        #pragma unroll
        for (int k = 0; k < 16; k++) {
            float4 a0 = *(const float4*)&As[k][trow * 8];
            float4 a1 = *(const float4*)&As[k][trow * 8 + 4];
            float4 b0 = *(const float4*)&Bs[k][tcol * 8];
            float4 b1 = *(const float4*)&Bs[k][tcol * 8 + 4];
            float ra[8] = {a0.x, a0.y, a0.z, a0.w, a1.x, a1.y, a1.z, a1.w};
            float rb[8] = {b0.x, b0.y, b0.z, b0.w, b1.x, b1.y, b1.z, b1.w};
            #pragma unroll
            for (int i = 0; i < 8; i++)
                #pragma unroll
                for (int j = 0; j < 8; j++) acc[i][j] = fmaf(ra[i], rb[j], acc[i][j]);
        }
        __syncthreads();
    }

    #pragma unroll
    for (int i = 0; i < 8; i++) {
        int gr = row0 + trow * 8 + i;
        if (gr < NN) {
            float4 v0 = make_float4(acc[i][0], acc[i][1], acc[i][2], acc[i][3]);
            float4 v1 = make_float4(acc[i][4], acc[i][5], acc[i][6], acc[i][7]);
            *(float4*)(g_xw1 + (size_t)gr * NH + tcol * 8)     = v0;
            *(float4*)(g_xw1 + (size_t)gr * NH + tcol * 8 + 4) = v1;
        }
    }
}

// ------------------------------------------- prop1: h = relu(A_norm @ xw1 + b1)
// one warp per node, 4 feats (1 float4) per lane.
__global__ void __launch_bounds__(256) k_prop1(const float* __restrict__ b1) {
    int node = blockIdx.x * (blockDim.x >> 5) + (threadIdx.x >> 5);
    if (node >= NN) return;
    int lane = threadIdx.x & 31;

    float dv  = g_dinv[node];
    float slw = dv * dv;                                    // self-loop norm
    float4 a = *(const float4*)(g_xw1 + (size_t)node * NH + lane * 4);
    float4 acc = make_float4(a.x * slw, a.y * slw, a.z * slw, a.w * slw);

    int s = g_start[node], e = g_start[node + 1];
    int i = s;
    for (; i + 2 <= e; i += 2) {
        int   s0 = __ldg(&g_src[i]);
        int   s1 = __ldg(&g_src[i + 1]);
        float w0 = __ldg(&g_w[i]);
        float w1 = __ldg(&g_w[i + 1]);
        float4 v0 = *(const float4*)(g_xw1 + (size_t)s0 * NH + lane * 4);
        float4 v1 = *(const float4*)(g_xw1 + (size_t)s1 * NH + lane * 4);
        acc.x = fmaf(w0, v0.x, fmaf(w1, v1.x, acc.x));
        acc.y = fmaf(w0, v0.y, fmaf(w1, v1.y, acc.y));
        acc.z = fmaf(w0, v0.z, fmaf(w1, v1.z, acc.z));
        acc.w = fmaf(w0, v0.w, fmaf(w1, v1.w, acc.w));
    }
    if (i < e) {
        int   s0 = __ldg(&g_src[i]);
        float w0 = __ldg(&g_w[i]);
        float4 v0 = *(const float4*)(g_xw1 + (size_t)s0 * NH + lane * 4);
        acc.x = fmaf(w0, v0.x, acc.x);
        acc.y = fmaf(w0, v0.y, acc.y);
        acc.z = fmaf(w0, v0.z, acc.z);
        acc.w = fmaf(w0, v0.w, acc.w);
    }

    float4 b = *(const float4*)(b1 + lane * 4);
    float4 r;
    r.x = fmaxf(acc.x + b.x, 0.0f);
    r.y = fmaxf(acc.y + b.y, 0.0f);
    r.z = fmaxf(acc.z + b.z, 0.0f);
    r.w = fmaxf(acc.w + b.w, 0.0f);
    *(float4*)(g_h + (size_t)node * NH + lane * 4) = r;
}

// ------------------------------------------------------------- GEMM2: h@W2
// 64 nodes per block, smem-tiled, padded rows (132) to kill bank conflicts.
__global__ void __launch_bounds__(256) k_gemm2(const float* __restrict__ W2) {
    __shared__ float sh[64 * 132];
    __shared__ float sw[128 * 16];
    int tid = threadIdx.x;
    int n0  = blockIdx.x * 64;

    #pragma unroll
    for (int l = 0; l < 2; l++) {               // W2: 512 float4
        int idx = tid + l * 256;
        *(((float4*)sw) + idx) = *(((const float4*)W2) + idx);
    }
    #pragma unroll
    for (int l = 0; l < 8; l++) {               // h tile: 2048 float4
        int f4 = tid + l * 256;
        int r  = f4 >> 5;
        int c4 = f4 & 31;
        int gn = n0 + r;
        float4 v = (gn < NN) ? *(const float4*)(g_h + (size_t)gn * NH + c4 * 4)
                             : make_float4(0.f, 0.f, 0.f, 0.f);
        *(float4*)(sh + r * 132 + c4 * 4) = v;
    }
    __syncthreads();

    int nl = tid >> 2;       // 0..63 local node
    int cg = tid & 3;        // class group (4 classes)
    float4 acc = make_float4(0.f, 0.f, 0.f, 0.f);
    const float* hrow = sh + nl * 132;
    #pragma unroll
    for (int k = 0; k < 128; k++) {
        float hv = hrow[k];
        float4 w = *(((const float4*)(sw + k * 16)) + cg);
        acc.x = fmaf(hv, w.x, acc.x);
        acc.y = fmaf(hv, w.y, acc.y);
        acc.z = fmaf(hv, w.z, acc.z);
        acc.w = fmaf(hv, w.w, acc.w);
    }
    int gn = n0 + nl;
    if (gn < NN) *(float4*)(g_hw2 + (size_t)gn * NC + cg * 4) = acc;
}

// -------------------- prop2 + b2 + log_softmax fused: out = logsm(A@hw2 + b2)
// one warp per node; lanes 0..15 hold the 16 classes.
__global__ void __launch_bounds__(256) k_prop2(const float* __restrict__ b2,
                                               float* __restrict__ out) {
    int node = blockIdx.x * (blockDim.x >> 5) + (threadIdx.x >> 5);
    if (node >= NN) return;
    int lane = threadIdx.x & 31;

    float dv  = g_dinv[node];
    float slw = dv * dv;
    float acc = 0.0f;
    if (lane < 16) acc = g_hw2[(size_t)node * NC + lane] * slw;

    int s = g_start[node], e = g_start[node + 1];
    for (int i = s; i < e; i++) {
        int   src = __ldg(&g_src[i]);
        float w   = __ldg(&g_w[i]);
        if (lane < 16) acc = fmaf(w, __ldg(&g_hw2[(size_t)src * NC + lane]), acc);
    }

    float v = (lane < 16) ? (acc + b2[lane]) : -1e30f;
    float m = v;
    #pragma unroll
    for (int off = 8; off; off >>= 1) m = fmaxf(m, __shfl_xor_sync(0xffffffffu, m, off));
    float ex  = expf(v - m);
    float sum = ex;
    #pragma unroll
    for (int off = 8; off; off >>= 1) sum += __shfl_xor_sync(0xffffffffu, sum, off);
    float res = v - m - logf(sum);
    if (lane < 16) out[(size_t)node * NC + lane] = res;
}

// ---------------------------------------------------------------- launcher
extern "C" void kernel_launch(void* const* d_in, const int* in_sizes, int n_in,
                              void* d_out, int out_size) {
    const float* features = (const float*)d_in[0];
    const int*   ei       = (const int*)d_in[1];
    const float* ew       = (const float*)d_in[2];
    const float* W1       = (const float*)d_in[3];
    const float* b1       = (const float*)d_in[4];
    const float* W2       = (const float*)d_in[5];
    const float* b2       = (const float*)d_in[6];
    float* out = (float*)d_out;

    k_init   <<<(NN + 255) / 256, 256>>>();
    k_deg    <<<(EE + 255) / 256, 256>>>(ei, ew);
    k_dinv   <<<(NN + 255) / 256, 256>>>();
    k_scan   <<<1, 1024>>>();
    k_scatter<<<(EE + 255) / 256, 256>>>(ei, ew);

    k_gemm1  <<<(NN + 127) / 128, 256>>>(features, W1);
    k_prop1  <<<(NN + 7) / 8, 256>>>(b1);
    k_gemm2  <<<(NN + 63) / 64, 256>>>(W2);
    k_prop2  <<<(NN + 7) / 8, 256>>>(b2, out);
}

// round 3
// speedup vs baseline: 1.4212x; 1.4212x over previous
#include <cuda_runtime.h>
#include <cuda_fp16.h>
#include <math.h>

#define NN 100000
#define EE 3200000
#define NF 256
#define NH 128
#define NC 16
#define SCAN_NBLK ((NN + 1023) / 1024)

// ---- static device scratch (no allocations allowed) ----
__device__ float   g_deg[NN];
__device__ float   g_dinv[NN];
__device__ int     g_cnt[NN];
__device__ int     g_start[NN + 1];
__device__ int     g_cursor[NN];
__device__ int     g_bsum[256];
__device__ int     g_src[EE];
__device__ float   g_w[EE];
__device__ __half2 g_xw1h[(size_t)NN * (NH / 2)];  // features @ W1, fp16
__device__ float   g_h[(size_t)NN * NH];           // relu(prop(xw1)+b1)
__device__ float   g_hw2[(size_t)NN * NC];         // h @ W2

// ---------------------------------------------------------------- init
__global__ void k_init() {
    int i = blockIdx.x * blockDim.x + threadIdx.x;
    if (i < NN) { g_deg[i] = 1.0f; g_cnt[i] = 0; }  // deg starts at 1 (self-loop)
}

// ------------------------------------------------------- degree + counts
__global__ void k_deg(const int* __restrict__ ei, const float* __restrict__ ew) {
    int e = blockIdx.x * blockDim.x + threadIdx.x;
    if (e < EE) {
        int c = ei[EE + e];
        atomicAdd(&g_deg[c], ew[e]);
        atomicAdd(&g_cnt[c], 1);
    }
}

__global__ void k_dinv() {
    int i = blockIdx.x * blockDim.x + threadIdx.x;
    if (i < NN) {
        float d = g_deg[i];
        g_dinv[i] = d > 0.0f ? rsqrtf(d) : 0.0f;
    }
}

// ------------------------------------------ 3-phase scan, full-chip parallel
__global__ void __launch_bounds__(1024) k_scan1() {
    __shared__ int wsum[32];
    int t = threadIdx.x, lane = t & 31, warp = t >> 5;
    int i = blockIdx.x * 1024 + t;
    int v = (i < NN) ? g_cnt[i] : 0;
    int x = v;
    #pragma unroll
    for (int off = 1; off < 32; off <<= 1) {
        int y = __shfl_up_sync(0xffffffffu, x, off);
        if (lane >= off) x += y;
    }
    if (lane == 31) wsum[warp] = x;
    __syncthreads();
    if (warp == 0) {
        int s = wsum[lane];
        #pragma unroll
        for (int off = 1; off < 32; off <<= 1) {
            int y = __shfl_up_sync(0xffffffffu, s, off);
            if (lane >= off) s += y;
        }
        wsum[lane] = s;
    }
    __syncthreads();
    int incl = x + (warp > 0 ? wsum[warp - 1] : 0);
    if (i < NN) g_start[i] = incl - v;           // local exclusive
    if (t == 1023) g_bsum[blockIdx.x] = incl;    // block total
}

__global__ void k_scan2() {
    // single block, 128 threads: scan SCAN_NBLK (98) block sums -> exclusive
    int t = threadIdx.x, lane = t & 31, warp = t >> 5;
    __shared__ int wsum[4];
    int v = (t < SCAN_NBLK) ? g_bsum[t] : 0;
    int x = v;
    #pragma unroll
    for (int off = 1; off < 32; off <<= 1) {
        int y = __shfl_up_sync(0xffffffffu, x, off);
        if (lane >= off) x += y;
    }
    if (lane == 31) wsum[warp] = x;
    __syncthreads();
    int woff = 0;
    for (int w = 0; w < warp; w++) woff += wsum[w];
    int incl = x + woff;
    if (t < SCAN_NBLK) g_bsum[t] = incl - v;     // exclusive block offset
    if (t == SCAN_NBLK - 1) g_start[NN] = incl;  // grand total
}

__global__ void __launch_bounds__(1024) k_scan3() {
    int i = blockIdx.x * 1024 + threadIdx.x;
    if (i < NN) {
        int s = g_start[i] + g_bsum[blockIdx.x];
        g_start[i]  = s;
        g_cursor[i] = s;
    }
}

// ------------------------------------------------- scatter edges into CSC + norm
__global__ void k_scatter(const int* __restrict__ ei, const float* __restrict__ ew) {
    int e = blockIdx.x * blockDim.x + threadIdx.x;
    if (e < EE) {
        int r = ei[e];
        int c = ei[EE + e];
        float nrm = g_dinv[r] * ew[e] * g_dinv[c];
        int pos = atomicAdd(&g_cursor[c], 1);
        g_src[pos] = r;
        g_w[pos]   = nrm;
    }
}

// ------------------------------------------------------------- GEMM1: X@W1
// M=100000, K=256, N=128.  BM=128, BN=128, BK=16, 8x8 per thread, 256 threads.
// Output stored as fp16 (half2) for the L2-gather-bound prop1.
__global__ void __launch_bounds__(256) k_gemm1(const float* __restrict__ A,
                                               const float* __restrict__ B) {
    __shared__ float As[16][128];
    __shared__ float Bs[16][128];
    const int tid  = threadIdx.x;
    const int trow = tid >> 4;   // 0..15
    const int tcol = tid & 15;   // 0..15
    const int row0 = blockIdx.x * 128;

    float acc[8][8];
    #pragma unroll
    for (int i = 0; i < 8; i++)
        #pragma unroll
        for (int j = 0; j < 8; j++) acc[i][j] = 0.0f;

    for (int k0 = 0; k0 < NF; k0 += 16) {
        #pragma unroll
        for (int l = 0; l < 2; l++) {            // A tile: 512 float4
            int f4 = tid + l * 256;
            int r  = f4 >> 2;
            int kc = (f4 & 3) << 2;
            int gr = row0 + r;
            float4 v = make_float4(0.f, 0.f, 0.f, 0.f);
            if (gr < NN) v = *(const float4*)(A + (size_t)gr * NF + k0 + kc);
            As[kc + 0][r] = v.x; As[kc + 1][r] = v.y;
            As[kc + 2][r] = v.z; As[kc + 3][r] = v.w;
        }
        #pragma unroll
        for (int l = 0; l < 2; l++) {            // B tile: 512 float4
            int f4 = tid + l * 256;
            int r  = f4 >> 5;
            int c4 = f4 & 31;
            float4 v = *(const float4*)(B + (size_t)(k0 + r) * NH + c4 * 4);
            *(((float4*)&Bs[r][0]) + c4) = v;
        }
        __syncthreads();
        #pragma unroll
        for (int k = 0; k < 16; k++) {
            float4 a0 = *(const float4*)&As[k][trow * 8];
            float4 a1 = *(const float4*)&As[k][trow * 8 + 4];
            float4 b0 = *(const float4*)&Bs[k][tcol * 8];
            float4 b1 = *(const float4*)&Bs[k][tcol * 8 + 4];
            float ra[8] = {a0.x, a0.y, a0.z, a0.w, a1.x, a1.y, a1.z, a1.w};
            float rb[8] = {b0.x, b0.y, b0.z, b0.w, b1.x, b1.y, b1.z, b1.w};
            #pragma unroll
            for (int i = 0; i < 8; i++)
                #pragma unroll
                for (int j = 0; j < 8; j++) acc[i][j] = fmaf(ra[i], rb[j], acc[i][j]);
        }
        __syncthreads();
    }

    #pragma unroll
    for (int i = 0; i < 8; i++) {
        int gr = row0 + trow * 8 + i;
        if (gr < NN) {
            __half2 h0 = __floats2half2_rn(acc[i][0], acc[i][1]);
            __half2 h1 = __floats2half2_rn(acc[i][2], acc[i][3]);
            __half2 h2 = __floats2half2_rn(acc[i][4], acc[i][5]);
            __half2 h3 = __floats2half2_rn(acc[i][6], acc[i][7]);
            uint4 pk;
            pk.x = *(unsigned*)&h0; pk.y = *(unsigned*)&h1;
            pk.z = *(unsigned*)&h2; pk.w = *(unsigned*)&h3;
            *(uint4*)(g_xw1h + (size_t)gr * 64 + tcol * 4) = pk;
        }
    }
}

// ------------------------------------------- prop1: h = relu(A_norm @ xw1 + b1)
// one warp per node, 4 feats (one 8-byte half2x2) per lane.
__device__ __forceinline__ float4 ld_xw1_row4(int node, int lane) {
    uint2 raw = *reinterpret_cast<const uint2*>(g_xw1h + (size_t)node * 64 + lane * 2);
    __half2 a0 = *reinterpret_cast<__half2*>(&raw.x);
    __half2 a1 = *reinterpret_cast<__half2*>(&raw.y);
    float2 f0 = __half22float2(a0);
    float2 f1 = __half22float2(a1);
    return make_float4(f0.x, f0.y, f1.x, f1.y);
}

__global__ void __launch_bounds__(256) k_prop1(const float* __restrict__ b1) {
    int node = blockIdx.x * (blockDim.x >> 5) + (threadIdx.x >> 5);
    if (node >= NN) return;
    int lane = threadIdx.x & 31;

    float dv  = g_dinv[node];
    float slw = dv * dv;                                    // self-loop norm
    float4 a = ld_xw1_row4(node, lane);
    float4 acc = make_float4(a.x * slw, a.y * slw, a.z * slw, a.w * slw);

    int s = g_start[node], e = g_start[node + 1];
    int i = s;
    for (; i + 2 <= e; i += 2) {
        int   s0 = __ldg(&g_src[i]);
        int   s1 = __ldg(&g_src[i + 1]);
        float w0 = __ldg(&g_w[i]);
        float w1 = __ldg(&g_w[i + 1]);
        float4 v0 = ld_xw1_row4(s0, lane);
        float4 v1 = ld_xw1_row4(s1, lane);
        acc.x = fmaf(w0, v0.x, fmaf(w1, v1.x, acc.x));
        acc.y = fmaf(w0, v0.y, fmaf(w1, v1.y, acc.y));
        acc.z = fmaf(w0, v0.z, fmaf(w1, v1.z, acc.z));
        acc.w = fmaf(w0, v0.w, fmaf(w1, v1.w, acc.w));
    }
    if (i < e) {
        int   s0 = __ldg(&g_src[i]);
        float w0 = __ldg(&g_w[i]);
        float4 v0 = ld_xw1_row4(s0, lane);
        acc.x = fmaf(w0, v0.x, acc.x);
        acc.y = fmaf(w0, v0.y, acc.y);
        acc.z = fmaf(w0, v0.z, acc.z);
        acc.w = fmaf(w0, v0.w, acc.w);
    }

    float4 b = *(const float4*)(b1 + lane * 4);
    float4 r;
    r.x = fmaxf(acc.x + b.x, 0.0f);
    r.y = fmaxf(acc.y + b.y, 0.0f);
    r.z = fmaxf(acc.z + b.z, 0.0f);
    r.w = fmaxf(acc.w + b.w, 0.0f);
    *(float4*)(g_h + (size_t)node * NH + lane * 4) = r;
}

// ------------------------------------------------------------- GEMM2: h@W2
// 64 nodes per block, smem-tiled, padded rows (132) to kill bank conflicts.
__global__ void __launch_bounds__(256) k_gemm2(const float* __restrict__ W2) {
    __shared__ float sh[64 * 132];
    __shared__ float sw[128 * 16];
    int tid = threadIdx.x;
    int n0  = blockIdx.x * 64;

    #pragma unroll
    for (int l = 0; l < 2; l++) {               // W2: 512 float4
        int idx = tid + l * 256;
        *(((float4*)sw) + idx) = *(((const float4*)W2) + idx);
    }
    #pragma unroll
    for (int l = 0; l < 8; l++) {               // h tile: 2048 float4
        int f4 = tid + l * 256;
        int r  = f4 >> 5;
        int c4 = f4 & 31;
        int gn = n0 + r;
        float4 v = (gn < NN) ? *(const float4*)(g_h + (size_t)gn * NH + c4 * 4)
                             : make_float4(0.f, 0.f, 0.f, 0.f);
        *(float4*)(sh + r * 132 + c4 * 4) = v;
    }
    __syncthreads();

    int nl = tid >> 2;       // 0..63 local node
    int cg = tid & 3;        // class group (4 classes)
    float4 acc = make_float4(0.f, 0.f, 0.f, 0.f);
    const float* hrow = sh + nl * 132;
    #pragma unroll
    for (int k = 0; k < 128; k++) {
        float hv = hrow[k];
        float4 w = *(((const float4*)(sw + k * 16)) + cg);
        acc.x = fmaf(hv, w.x, acc.x);
        acc.y = fmaf(hv, w.y, acc.y);
        acc.z = fmaf(hv, w.z, acc.z);
        acc.w = fmaf(hv, w.w, acc.w);
    }
    int gn = n0 + nl;
    if (gn < NN) *(float4*)(g_hw2 + (size_t)gn * NC + cg * 4) = acc;
}

// -------------------- prop2 + b2 + log_softmax fused: out = logsm(A@hw2 + b2)
// one warp per node; lanes split edges into two streams (stream = lane>>4,
// class = lane&15), combined by shfl_xor(16).
__global__ void __launch_bounds__(256) k_prop2(const float* __restrict__ b2,
                                               float* __restrict__ out) {
    int node = blockIdx.x * (blockDim.x >> 5) + (threadIdx.x >> 5);
    if (node >= NN) return;
    int lane = threadIdx.x & 31;
    int half = lane >> 4;
    int cls  = lane & 15;

    float dv  = g_dinv[node];
    float acc = (half == 0) ? g_hw2[(size_t)node * NC + cls] * dv * dv : 0.0f;

    int s = g_start[node], e = g_start[node + 1];
    for (int i = s + half; i < e; i += 2) {
        int   src = __ldg(&g_src[i]);
        float w   = __ldg(&g_w[i]);
        acc = fmaf(w, __ldg(&g_hw2[(size_t)src * NC + cls]), acc);
    }
    acc += __shfl_xor_sync(0xffffffffu, acc, 16);

    float v = acc + b2[cls];
    float m = v;
    #pragma unroll
    for (int off = 8; off; off >>= 1) m = fmaxf(m, __shfl_xor_sync(0xffffffffu, m, off));
    float ex  = expf(v - m);
    float sum = ex;
    #pragma unroll
    for (int off = 8; off; off >>= 1) sum += __shfl_xor_sync(0xffffffffu, sum, off);
    float res = v - m - logf(sum);
    if (lane < 16) out[(size_t)node * NC + lane] = res;
}

// ---------------------------------------------------------------- launcher
extern "C" void kernel_launch(void* const* d_in, const int* in_sizes, int n_in,
                              void* d_out, int out_size) {
    const float* features = (const float*)d_in[0];
    const int*   ei       = (const int*)d_in[1];
    const float* ew       = (const float*)d_in[2];
    const float* W1       = (const float*)d_in[3];
    const float* b1       = (const float*)d_in[4];
    const float* W2       = (const float*)d_in[5];
    const float* b2       = (const float*)d_in[6];
    float* out = (float*)d_out;

    k_init   <<<(NN + 255) / 256, 256>>>();
    k_deg    <<<(EE + 255) / 256, 256>>>(ei, ew);
    k_dinv   <<<(NN + 255) / 256, 256>>>();
    k_scan1  <<<SCAN_NBLK, 1024>>>();
    k_scan2  <<<1, 128>>>();
    k_scan3  <<<SCAN_NBLK, 1024>>>();
    k_scatter<<<(EE + 255) / 256, 256>>>(ei, ew);

    k_gemm1  <<<(NN + 127) / 128, 256>>>(features, W1);
    k_prop1  <<<(NN + 7) / 8, 256>>>(b1);
    k_gemm2  <<<(NN + 63) / 64, 256>>>(W2);
    k_prop2  <<<(NN + 7) / 8, 256>>>(b2, out);
}